// round 1
// baseline (speedup 1.0000x reference)
#include <cuda_runtime.h>

#define NB 16
#define NQT 2048
#define NKT 2048
#define ND 1024
#define BM 16
#define BN 8
#define NTHREADS 256
#define NV4 16   // 16 float4 (=64 floats) per thread slice; 16 lanes cover D=1024

// scratch for mean(V) rows (invalid-q output) -- no cudaMalloc allowed
__device__ float g_meanV[NB * ND];

union F2U { unsigned long long u; float2 f; };

__device__ __forceinline__ void ffma2(unsigned long long& d, unsigned long long a, unsigned long long b) {
    asm("fma.rn.f32x2 %0, %1, %2, %0;" : "+l"(d) : "l"(a), "l"(b));
}
__device__ __forceinline__ unsigned long long fmul2(unsigned long long a, unsigned long long b) {
    unsigned long long r;
    asm("mul.rn.f32x2 %0, %1, %2;" : "=l"(r) : "l"(a), "l"(b));
    return r;
}
__device__ __forceinline__ unsigned long long fadd2(unsigned long long a, unsigned long long b) {
    unsigned long long r;
    asm("add.rn.f32x2 %0, %1, %2;" : "=l"(r) : "l"(a), "l"(b));
    return r;
}

// mean over the FULL KT axis of V (reference gives uniform softmax on fully
// masked rows => output is mean of all V rows, independent of K_lengths).
__global__ void meanv_kernel(const float* __restrict__ V) {
    __shared__ float red[256];
    const int b = blockIdx.y;
    const int d = blockIdx.x * 64 + (threadIdx.x & 63);
    const int kc = threadIdx.x >> 6;   // 4 k-chunks of 512
    const float* vp = V + ((size_t)b * NKT + (size_t)kc * 512) * ND + d;
    float s = 0.f;
    #pragma unroll 8
    for (int k = 0; k < 512; ++k) s += vp[(size_t)k * ND];
    red[threadIdx.x] = s;
    __syncthreads();
    if (threadIdx.x < 64) {
        float tot = red[threadIdx.x] + red[threadIdx.x + 64]
                  + red[threadIdx.x + 128] + red[threadIdx.x + 192];
        g_meanV[b * ND + blockIdx.x * 64 + threadIdx.x] = tot * (1.0f / (float)NKT);
    }
}

__global__ void __launch_bounds__(NTHREADS, 1)
attn_kernel(const float* __restrict__ Q, const float* __restrict__ K,
            const float* __restrict__ V, const int* __restrict__ Qlens,
            const int* __restrict__ Klens, float* __restrict__ Out)
{
    extern __shared__ float smem[];
    float* sK = smem;            // [BN][ND]
    float* sV = smem + BN * ND;  // [BN][ND]

    const int b    = blockIdx.y;
    const int tid  = threadIdx.x;
    const int lane = tid & 31;
    const int warp = tid >> 5;
    const int lq   = lane >> 4;   // 0/1: which of the warp's 2 q rows
    const int sl   = lane & 15;   // d-slice index (strided float4 mapping)
    const int q    = blockIdx.x * BM + warp * 2 + lq;

    const int Qlen = Qlens[b];
    const int Klen = Klens[b];

    float* outp = Out + ((size_t)b * NQT + q) * ND;

    // whole q-tile masked out -> uniform attention -> mean(V)
    if (blockIdx.x * BM >= Qlen) {
        const float4* mv = (const float4*)(g_meanV + b * ND);
        float4* op = (float4*)outp;
        #pragma unroll
        for (int i = 0; i < NV4; ++i) op[i * 16 + sl] = mv[i * 16 + sl];
        return;
    }

    const bool qvalid = (q < Qlen);

    // Q slice in registers. Invalid rows get zeros (keeps warp convergent,
    // results discarded at the end).
    ulonglong2 q2[NV4];
    if (qvalid) {
        const ulonglong2* qp = (const ulonglong2*)(Q + ((size_t)b * NQT + q) * ND);
        #pragma unroll
        for (int i = 0; i < NV4; ++i) q2[i] = qp[i * 16 + sl];
    } else {
        #pragma unroll
        for (int i = 0; i < NV4; ++i) { q2[i].x = 0ull; q2[i].y = 0ull; }
    }

    unsigned long long o2[2 * NV4];   // 32 packed f32x2 accumulators (64 floats)
    #pragma unroll
    for (int i = 0; i < 2 * NV4; ++i) o2[i] = 0ull;

    float m = __int_as_float(0xff800000);  // -inf
    float l = 0.f;

    const float* Kb = K + (size_t)b * NKT * ND;
    const float* Vb = V + (size_t)b * NKT * ND;
    const int nTiles = (Klen + BN - 1) / BN;   // k >= Klen contributes exactly 0

    for (int t = 0; t < nTiles; ++t) {
        const int base = t * BN;
        {   // cooperative tile load (KT is a multiple of BN -> never OOB)
            const float4* kg = (const float4*)(Kb + (size_t)base * ND);
            const float4* vg = (const float4*)(Vb + (size_t)base * ND);
            float4* ks = (float4*)sK;
            float4* vs = (float4*)sV;
            #pragma unroll
            for (int i = 0; i < (BN * ND / 4) / NTHREADS; ++i) {
                const int idx = tid + i * NTHREADS;
                ks[idx] = kg[idx];
                vs[idx] = vg[idx];
            }
        }
        __syncthreads();

        const int jmax = min(BN, Klen - base);  // uniform across block
        float s[BN];
        #pragma unroll
        for (int j = 0; j < BN; ++j) {
            float acc = 0.f;
            if (j < jmax) {
                const ulonglong2* kr = (const ulonglong2*)(sK + j * ND);
                unsigned long long a0 = 0ull, a1 = 0ull, a2 = 0ull, a3 = 0ull;
                #pragma unroll
                for (int i = 0; i < NV4; i += 2) {
                    ulonglong2 ka = kr[i * 16 + sl];
                    ulonglong2 kb = kr[(i + 1) * 16 + sl];
                    ffma2(a0, q2[i].x, ka.x);
                    ffma2(a1, q2[i].y, ka.y);
                    ffma2(a2, q2[i + 1].x, kb.x);
                    ffma2(a3, q2[i + 1].y, kb.y);
                }
                a0 = fadd2(a0, a1);
                a2 = fadd2(a2, a3);
                a0 = fadd2(a0, a2);
                F2U cv; cv.u = a0;
                acc = cv.f.x + cv.f.y;
                // reduce across the 16 lanes of this row group
                acc += __shfl_xor_sync(0xffffffffu, acc, 8);
                acc += __shfl_xor_sync(0xffffffffu, acc, 4);
                acc += __shfl_xor_sync(0xffffffffu, acc, 2);
                acc += __shfl_xor_sync(0xffffffffu, acc, 1);
            }
            s[j] = acc;
        }

        float mnew = m;
        #pragma unroll
        for (int j = 0; j < BN; ++j) if (j < jmax) mnew = fmaxf(mnew, s[j]);

        if (mnew > m) {   // rescale only when the running max actually moves
            const float scale = __expf(m - mnew);
            l *= scale;
            F2U sc; sc.f.x = scale; sc.f.y = scale;
            #pragma unroll
            for (int i = 0; i < 2 * NV4; ++i) o2[i] = fmul2(o2[i], sc.u);
            m = mnew;
        }

        #pragma unroll
        for (int j = 0; j < BN; ++j) {
            if (j < jmax) {
                const float p = __expf(s[j] - m);
                l += p;
                F2U pp; pp.f.x = p; pp.f.y = p;
                const ulonglong2* vr = (const ulonglong2*)(sV + j * ND);
                #pragma unroll
                for (int i = 0; i < NV4; ++i) {
                    ulonglong2 vv = vr[i * 16 + sl];
                    ffma2(o2[2 * i],     pp.u, vv.x);
                    ffma2(o2[2 * i + 1], pp.u, vv.y);
                }
            }
        }
        __syncthreads();
    }

    if (qvalid) {
        const float inv = 1.0f / l;   // l identical across the 16-lane group
        F2U iv; iv.f.x = inv; iv.f.y = inv;
        ulonglong2* op = (ulonglong2*)outp;
        #pragma unroll
        for (int i = 0; i < NV4; ++i) {
            ulonglong2 w;
            w.x = fmul2(o2[2 * i],     iv.u);
            w.y = fmul2(o2[2 * i + 1], iv.u);
            op[i * 16 + sl] = w;
        }
    } else {
        const float4* mv = (const float4*)(g_meanV + b * ND);
        float4* op = (float4*)outp;
        #pragma unroll
        for (int i = 0; i < NV4; ++i) op[i * 16 + sl] = mv[i * 16 + sl];
    }
}

extern "C" void kernel_launch(void* const* d_in, const int* in_sizes, int n_in,
                              void* d_out, int out_size) {
    (void)in_sizes; (void)n_in; (void)out_size;
    const float* Q  = (const float*)d_in[0];
    const float* K  = (const float*)d_in[1];
    const float* V  = (const float*)d_in[2];
    const int*   Ql = (const int*)d_in[3];
    const int*   Kl = (const int*)d_in[4];
    float* Out = (float*)d_out;

    meanv_kernel<<<dim3(ND / 64, NB), 256>>>(V);

    const int smem_bytes = 2 * BN * ND * (int)sizeof(float);  // 64 KiB
    cudaFuncSetAttribute((const void*)attn_kernel,
                         cudaFuncAttributeMaxDynamicSharedMemorySize, smem_bytes);
    attn_kernel<<<dim3(NQT / BM, NB), NTHREADS, smem_bytes>>>(Q, K, V, Ql, Kl, Out);
}

// round 4
// speedup vs baseline: 2.4434x; 2.4434x over previous
#include <cuda_runtime.h>
#include <cstdint>

#define NB 16
#define NQT 2048
#define NKT 2048
#define ND 1024
#define BM 16
#define BN 8
#define NTHREADS 256

// float-unit offsets in dynamic smem
#define OFF_K    0        // [2][BN][1024]  (double-buffered K)
#define OFF_V    16384    // [2][BN][1024]  (double-buffered V)
#define OFF_PART 32768    // [4 groups][32 pairs][68]
#define OFF_S    41472    // [4][32] scores
#define OFF_P    41600    // [4][32] probabilities
#define SMEM_FLOATS 41728 // 166,912 bytes

__device__ float g_meanV[NB * ND];

#define NEG_INF __int_as_float(0xff800000)

union F2U { unsigned long long u; float2 f; };

__device__ __forceinline__ void ffma2(unsigned long long& d, unsigned long long a, unsigned long long b) {
    asm("fma.rn.f32x2 %0, %1, %2, %0;" : "+l"(d) : "l"(a), "l"(b));
}
__device__ __forceinline__ unsigned long long fmul2(unsigned long long a, unsigned long long b) {
    unsigned long long r;
    asm("mul.rn.f32x2 %0, %1, %2;" : "=l"(r) : "l"(a), "l"(b));
    return r;
}
__device__ __forceinline__ void cp16(unsigned int d, const void* s) {
    asm volatile("cp.async.cg.shared.global [%0], [%1], 16;" :: "r"(d), "l"(s) : "memory");
}

// mean over FULL KT axis of V (fully masked q-rows have uniform softmax)
__global__ void meanv_kernel(const float* __restrict__ V) {
    __shared__ float red[256];
    const int b = blockIdx.y;
    const int d = blockIdx.x * 64 + (threadIdx.x & 63);
    const int kc = threadIdx.x >> 6;
    const float* vp = V + ((size_t)b * NKT + (size_t)kc * 512) * ND + d;
    float s = 0.f;
    #pragma unroll 8
    for (int k = 0; k < 512; ++k) s += vp[(size_t)k * ND];
    red[threadIdx.x] = s;
    __syncthreads();
    if (threadIdx.x < 64) {
        float tot = red[threadIdx.x] + red[threadIdx.x + 64]
                  + red[threadIdx.x + 128] + red[threadIdx.x + 192];
        g_meanV[b * ND + blockIdx.x * 64 + threadIdx.x] = tot * (1.0f / (float)NKT);
    }
}

__device__ __forceinline__ void issue_tile(unsigned int sb, const float* Kb, const float* Vb,
                                           int t, int c, int tid) {
    const float4* kg = (const float4*)(Kb + (size_t)t * BN * ND);
    const float4* vg = (const float4*)(Vb + (size_t)t * BN * ND);
    const unsigned int kd = sb + (unsigned int)c * 32768u + (unsigned int)tid * 16u;
    const unsigned int vd = kd + 65536u;
    #pragma unroll
    for (int i = 0; i < 8; ++i) {
        cp16(kd + (unsigned int)i * 4096u, kg + tid + i * 256);
        cp16(vd + (unsigned int)i * 4096u, vg + tid + i * 256);
    }
}

__global__ void __launch_bounds__(NTHREADS, 1)
attn_kernel(const float* __restrict__ Q, const float* __restrict__ K,
            const float* __restrict__ V, const int* __restrict__ Qlens,
            const int* __restrict__ Klens, float* __restrict__ Out)
{
    extern __shared__ float smf[];
    const int tid = threadIdx.x;
    const int b   = blockIdx.y;
    const int g   = tid >> 6;      // group 0..3 (64 threads each)
    const int gt  = tid & 63;      // thread-in-group: strided d-slice {gt, gt+64, gt+128, gt+192} (float4 units)
    const int q0  = blockIdx.x * BM + g * 4;   // this thread's 4 q-rows: q0..q0+3

    const int Qlen = Qlens[b];
    const int Klen = Klens[b];

    // fully masked q-tile -> uniform attention -> mean(V)
    if (blockIdx.x * BM >= Qlen) {
        const float4* mv = (const float4*)(g_meanV + b * ND);
        #pragma unroll
        for (int r = 0; r < 4; ++r) {
            float4* op = (float4*)(Out + ((size_t)b * NQT + q0 + r) * ND);
            #pragma unroll
            for (int i = 0; i < 4; ++i) op[gt + 64 * i] = mv[gt + 64 * i];
        }
        return;
    }

    const float* Kb = K + (size_t)b * NKT * ND;
    const float* Vb = V + (size_t)b * NKT * ND;
    const int nT = (Klen + BN - 1) / BN;

    const unsigned int sb = (unsigned int)__cvta_generic_to_shared(smf);

    // prefetch tile 0
    issue_tile(sb, Kb, Vb, 0, 0, tid);
    asm volatile("cp.async.commit_group;" ::: "memory");

    // Q slices in registers: 4 rows x 16 floats (8 f32x2 each). Invalid rows zero.
    unsigned long long q2[4][8];
    #pragma unroll
    for (int r = 0; r < 4; ++r) {
        if (q0 + r < Qlen) {
            const float4* qp = (const float4*)(Q + ((size_t)b * NQT + q0 + r) * ND);
            #pragma unroll
            for (int i = 0; i < 4; ++i) {
                const ulonglong2 v = ((const ulonglong2*)qp)[gt + 64 * i];
                q2[r][2 * i]     = v.x;
                q2[r][2 * i + 1] = v.y;
            }
        } else {
            #pragma unroll
            for (int u = 0; u < 8; ++u) q2[r][u] = 0ull;
        }
    }

    unsigned long long o2[4][8];
    #pragma unroll
    for (int r = 0; r < 4; ++r)
        #pragma unroll
        for (int u = 0; u < 8; ++u) o2[r][u] = 0ull;

    float m[4] = {NEG_INF, NEG_INF, NEG_INF, NEG_INF};
    float l[4] = {0.f, 0.f, 0.f, 0.f};

    float* part = smf + OFF_PART + g * (32 * 68);
    const float* sSc = smf + OFF_S + g * 32;
    const float* sPr = smf + OFF_P + g * 32;

    for (int t = 0; t < nT; ++t) {
        const int c = t & 1;
        if (t + 1 < nT) issue_tile(sb, Kb, Vb, t + 1, (t + 1) & 1, tid);
        asm volatile("cp.async.commit_group;" ::: "memory");
        if (t + 1 < nT) { asm volatile("cp.async.wait_group 1;" ::: "memory"); }
        else            { asm volatile("cp.async.wait_group 0;" ::: "memory"); }
        __syncthreads();                               // (a) tile c ready for all

        const int jmax = min(BN, Klen - t * BN);
        const float* sK = smf + OFF_K + c * 8192;
        const float* sV = smf + OFF_V + c * 8192;

        // ---- QK partials: 4 rows x 8 k, each thread over its 16-float slice ----
        #pragma unroll
        for (int j = 0; j < BN; ++j) {
            const ulonglong2* kr = (const ulonglong2*)(sK + j * ND);
            unsigned long long kv[8];
            #pragma unroll
            for (int i = 0; i < 4; ++i) {
                const ulonglong2 kk = kr[gt + 64 * i];
                kv[2 * i] = kk.x; kv[2 * i + 1] = kk.y;
            }
            #pragma unroll
            for (int r = 0; r < 4; ++r) {
                unsigned long long a0 = 0ull, a1 = 0ull;
                #pragma unroll
                for (int u = 0; u < 8; u += 2) {
                    ffma2(a0, q2[r][u],     kv[u]);
                    ffma2(a1, q2[r][u + 1], kv[u + 1]);
                }
                F2U ca; ca.u = a0;
                F2U cb; cb.u = a1;
                part[(r * 8 + j) * 68 + gt] = (ca.f.x + ca.f.y) + (cb.f.x + cb.f.y);
            }
        }
        __syncthreads();                               // (b) partials visible

        // ---- reduce 64 partials per pair; one lane per pair; mask invalid k ----
        float myS = 0.f;
        if (gt < 32) {
            const float4* row4 = (const float4*)(part + gt * 68);
            float4 acc = row4[0];
            #pragma unroll
            for (int i = 1; i < 16; ++i) {
                const float4 v = row4[i];
                acc.x += v.x; acc.y += v.y; acc.z += v.z; acc.w += v.w;
            }
            myS = (acc.x + acc.y) + (acc.z + acc.w);
            if ((gt & 7) >= jmax) myS = NEG_INF;
            smf[OFF_S + g * 32 + gt] = myS;
        }
        __syncthreads();                               // (c) scores visible

        // ---- all threads: per-row tile max, running max update, O rescale ----
        const float4* ssv = (const float4*)sSc;
        #pragma unroll
        for (int r = 0; r < 4; ++r) {
            const float4 a = ssv[2 * r], bq = ssv[2 * r + 1];
            float tm = fmaxf(fmaxf(fmaxf(a.x, a.y), fmaxf(a.z, a.w)),
                             fmaxf(fmaxf(bq.x, bq.y), fmaxf(bq.z, bq.w)));
            if (tm > m[r]) {
                const float scale = __expf(m[r] - tm);
                l[r] *= scale;
                F2U sc; sc.f.x = scale; sc.f.y = scale;
                #pragma unroll
                for (int u = 0; u < 8; ++u) o2[r][u] = fmul2(o2[r][u], sc.u);
                m[r] = tm;
            }
        }
        // one exp per pair (lane gt<32 owns pair gt = r*8+j)
        if (gt < 32) {
            const int r = gt >> 3;
            const float pv = (myS == NEG_INF) ? 0.f : __expf(myS - m[r]);
            smf[OFF_P + g * 32 + gt] = pv;
        }
        __syncthreads();                               // (d) p visible

        // ---- PV: O += p * V, l += sum(p) ----
        #pragma unroll
        for (int j = 0; j < BN; ++j) {
            const float p0 = sPr[0 * 8 + j];
            const float p1 = sPr[1 * 8 + j];
            const float p2v = sPr[2 * 8 + j];
            const float p3 = sPr[3 * 8 + j];
            l[0] += p0; l[1] += p1; l[2] += p2v; l[3] += p3;

            const ulonglong2* vr = (const ulonglong2*)(sV + j * ND);
            unsigned long long vv[8];
            #pragma unroll
            for (int i = 0; i < 4; ++i) {
                const ulonglong2 vk = vr[gt + 64 * i];
                vv[2 * i] = vk.x; vv[2 * i + 1] = vk.y;
            }
            F2U pp0; pp0.f.x = p0;  pp0.f.y = p0;
            F2U pp1; pp1.f.x = p1;  pp1.f.y = p1;
            F2U pp2; pp2.f.x = p2v; pp2.f.y = p2v;
            F2U pp3; pp3.f.x = p3;  pp3.f.y = p3;
            #pragma unroll
            for (int u = 0; u < 8; ++u) {
                ffma2(o2[0][u], pp0.u, vv[u]);
                ffma2(o2[1][u], pp1.u, vv[u]);
                ffma2(o2[2][u], pp2.u, vv[u]);
                ffma2(o2[3][u], pp3.u, vv[u]);
            }
        }
        __syncthreads();                               // (e) buffers free for next issue
    }

    // ---- epilogue ----
    #pragma unroll
    for (int r = 0; r < 4; ++r) {
        float4* op = (float4*)(Out + ((size_t)b * NQT + q0 + r) * ND);
        if (q0 + r < Qlen) {
            const float inv = 1.0f / l[r];
            F2U iv; iv.f.x = inv; iv.f.y = inv;
            #pragma unroll
            for (int i = 0; i < 4; ++i) {
                ulonglong2 w;
                w.x = fmul2(o2[r][2 * i],     iv.u);
                w.y = fmul2(o2[r][2 * i + 1], iv.u);
                ((ulonglong2*)op)[gt + 64 * i] = w;
            }
        } else {
            const float4* mv = (const float4*)(g_meanV + b * ND);
            #pragma unroll
            for (int i = 0; i < 4; ++i) op[gt + 64 * i] = mv[gt + 64 * i];
        }
    }
}

extern "C" void kernel_launch(void* const* d_in, const int* in_sizes, int n_in,
                              void* d_out, int out_size) {
    (void)in_sizes; (void)n_in; (void)out_size;
    const float* Q  = (const float*)d_in[0];
    const float* K  = (const float*)d_in[1];
    const float* V  = (const float*)d_in[2];
    const int*   Ql = (const int*)d_in[3];
    const int*   Kl = (const int*)d_in[4];
    float* Out = (float*)d_out;

    meanv_kernel<<<dim3(ND / 64, NB), 256>>>(V);

    const int smem_bytes = SMEM_FLOATS * 4;  // 166,912 B
    cudaFuncSetAttribute((const void*)attn_kernel,
                         cudaFuncAttributeMaxDynamicSharedMemorySize, smem_bytes);
    attn_kernel<<<dim3(NQT / BM, NB), NTHREADS, smem_bytes>>>(Q, K, V, Ql, Kl, Out);
}

// round 6
// speedup vs baseline: 2.7045x; 1.1068x over previous
#include <cuda_runtime.h>
#include <cuda_bf16.h>
#include <cstdint>

#define NB 16
#define NQT 2048
#define NKT 2048
#define ND 1024
#define NTHREADS 256

#define NEG_INF __int_as_float(0xff800000)

// ---- device-global scratch (no cudaMalloc allowed) ----
// Q A-fragments: [b][qtile16 (128)][chunk16 (64)][hi/lo (2)][lane (32)] x uint4  = 134 MB
__device__ uint4 g_QA[16 * 128 * 64 * 2 * 32];
// K B-fragments: [b][ntile8 (256)][chunk16 (64)][hi/lo (2)][lane (32)] x uint2   = 134 MB
__device__ uint2 g_KB[16 * 256 * 64 * 2 * 32];
__device__ float g_meanV[NB * ND];

// ---- smem float offsets for attn kernel ----
#define OFF_VA   0        // [32 k-rows][512 floats] V d-half buffer A (64 KB)
#define OFF_VB   16384    // buffer B
#define OFF_S0   32768    // [16][36] scores, d-half 0
#define OFF_S1   33344    // [16][36] scores, d-half 1
#define OFF_PT   33920    // [32 j][20] probabilities (transposed)
#define OFF_MRUN 34560    // [16] running max
#define OFF_MNEW 34576    // [16] new max this tile
#define OFF_LT   34592    // [16] tile prob-sum
#define SMEM_FLOATS 34608 // 138,432 bytes

union F2U { unsigned long long u; float2 f; };

__device__ __forceinline__ void ffma2(unsigned long long& d, unsigned long long a, unsigned long long b) {
    asm("fma.rn.f32x2 %0, %1, %2, %0;" : "+l"(d) : "l"(a), "l"(b));
}
__device__ __forceinline__ unsigned long long fmul2(unsigned long long a, unsigned long long b) {
    unsigned long long r;
    asm("mul.rn.f32x2 %0, %1, %2;" : "=l"(r) : "l"(a), "l"(b));
    return r;
}
__device__ __forceinline__ void cp16(unsigned int d, const void* s) {
    asm volatile("cp.async.cg.shared.global [%0], [%1], 16;" :: "r"(d), "l"(s) : "memory");
}
__device__ __forceinline__ void cp_commit() { asm volatile("cp.async.commit_group;" ::: "memory"); }
__device__ __forceinline__ void cp_wait1() { asm volatile("cp.async.wait_group 1;" ::: "memory"); }

__device__ __forceinline__ void mma_bf16(float& c0, float& c1, float& c2, float& c3,
                                         const uint4& a, unsigned b0, unsigned b1) {
    asm volatile("mma.sync.aligned.m16n8k16.row.col.f32.bf16.bf16.f32 "
                 "{%0,%1,%2,%3},{%4,%5,%6,%7},{%8,%9},{%0,%1,%2,%3};"
                 : "+f"(c0), "+f"(c1), "+f"(c2), "+f"(c3)
                 : "r"(a.x), "r"(a.y), "r"(a.z), "r"(a.w), "r"(b0), "r"(b1));
}

__device__ __forceinline__ unsigned pack_bf16(float a, float b) {
    __nv_bfloat162 t = __floats2bfloat162_rn(a, b);  // .x = a (low half)
    unsigned r; memcpy(&r, &t, 4); return r;
}
__device__ __forceinline__ float bf16_res(float x) {   // residual after bf16 rounding
    return x - __bfloat162float(__float2bfloat16_rn(x));
}

// ---------------- precompute kernels ----------------

__global__ void meanv_kernel(const float* __restrict__ V) {
    __shared__ float red[256];
    const int b = blockIdx.y;
    const int d = blockIdx.x * 64 + (threadIdx.x & 63);
    const int kc = threadIdx.x >> 6;
    const float* vp = V + ((size_t)b * NKT + (size_t)kc * 512) * ND + d;
    float s = 0.f;
    #pragma unroll 8
    for (int k = 0; k < 512; ++k) s += vp[(size_t)k * ND];
    red[threadIdx.x] = s;
    __syncthreads();
    if (threadIdx.x < 64) {
        float tot = red[threadIdx.x] + red[threadIdx.x + 64]
                  + red[threadIdx.x + 128] + red[threadIdx.x + 192];
        g_meanV[b * ND + blockIdx.x * 64 + threadIdx.x] = tot * (1.0f / (float)NKT);
    }
}

// Q -> bf16 hi/lo A-fragment records
__global__ void qpack_kernel(const float* __restrict__ Q) {
    extern __shared__ float sq[];   // [16][1024]  64 KB
    const int qt = blockIdx.x, b = blockIdx.y, tid = threadIdx.x;
    const float4* src = (const float4*)(Q + ((size_t)(b * NQT + qt * 16)) * ND);
    #pragma unroll
    for (int i = 0; i < 16; ++i) ((float4*)sq)[tid + i * 256] = src[tid + i * 256];
    __syncthreads();
    const size_t base = (size_t)(b * 128 + qt) * 4096;   // 64 chunks * 2 * 32
    #pragma unroll
    for (int it = 0; it < 16; ++it) {
        const int id = tid + it * 256;
        const int rec = id >> 5, lane = id & 31;
        const int ch = rec >> 1, hl = rec & 1;
        const int r0 = lane >> 2, c = ch * 16 + (lane & 3) * 2;
        float v0 = sq[r0 * ND + c],           v1 = sq[r0 * ND + c + 1];
        float v2 = sq[(r0 + 8) * ND + c],     v3 = sq[(r0 + 8) * ND + c + 1];
        float v4 = sq[r0 * ND + c + 8],       v5 = sq[r0 * ND + c + 9];
        float v6 = sq[(r0 + 8) * ND + c + 8], v7 = sq[(r0 + 8) * ND + c + 9];
        if (hl) {
            v0 = bf16_res(v0); v1 = bf16_res(v1); v2 = bf16_res(v2); v3 = bf16_res(v3);
            v4 = bf16_res(v4); v5 = bf16_res(v5); v6 = bf16_res(v6); v7 = bf16_res(v7);
        }
        uint4 o;
        o.x = pack_bf16(v0, v1); o.y = pack_bf16(v2, v3);
        o.z = pack_bf16(v4, v5); o.w = pack_bf16(v6, v7);
        g_QA[base + (size_t)rec * 32 + lane] = o;
    }
}

// K -> bf16 hi/lo B-fragment records
__global__ void kpack_kernel(const float* __restrict__ K) {
    __shared__ float sk[8 * ND];   // 32 KB
    const int nt = blockIdx.x, b = blockIdx.y, tid = threadIdx.x;
    const float4* src = (const float4*)(K + ((size_t)(b * NKT + nt * 8)) * ND);
    #pragma unroll
    for (int i = 0; i < 8; ++i) ((float4*)sk)[tid + i * 256] = src[tid + i * 256];
    __syncthreads();
    const size_t base = (size_t)(b * 256 + nt) * 4096;
    #pragma unroll
    for (int it = 0; it < 16; ++it) {
        const int id = tid + it * 256;
        const int rec = id >> 5, lane = id & 31;
        const int ch = rec >> 1, hl = rec & 1;
        const int n = lane >> 2, c = ch * 16 + (lane & 3) * 2;
        float v0 = sk[n * ND + c],     v1 = sk[n * ND + c + 1];
        float v2 = sk[n * ND + c + 8], v3 = sk[n * ND + c + 9];
        if (hl) { v0 = bf16_res(v0); v1 = bf16_res(v1); v2 = bf16_res(v2); v3 = bf16_res(v3); }
        uint2 o;
        o.x = pack_bf16(v0, v1); o.y = pack_bf16(v2, v3);
        g_KB[base + (size_t)rec * 32 + lane] = o;
    }
}

// ---------------- attention kernel ----------------

__device__ __forceinline__ void fill_vhalf(unsigned int sb, int bufFloatOff,
                                           const float* Vb, int t, int hh, int tid) {
    const unsigned int dst = sb + (unsigned int)bufFloatOff * 4u + (unsigned int)tid * 16u;
    #pragma unroll
    for (int i = 0; i < 16; ++i) {
        const int idx = tid + i * 256;
        const int row = idx >> 7, c4 = idx & 127;
        cp16(dst + (unsigned int)i * 4096u,
             Vb + ((size_t)(t * 32 + row)) * ND + hh * 512 + c4 * 4);
    }
}

__global__ void __launch_bounds__(NTHREADS, 1)
attn_kernel(const float* __restrict__ V, const int* __restrict__ Qlens,
            const int* __restrict__ Klens, float* __restrict__ Out)
{
    extern __shared__ float smf[];
    const int tid  = threadIdx.x;
    const int qt   = blockIdx.x;
    const int b    = blockIdx.y;
    const int lane = tid & 31;
    const int w    = tid >> 5;
    const int h    = w >> 2;       // d-half for QK
    const int wn   = w & 3;        // n-tile for QK

    const int Qlen = Qlens[b];
    const int Klen = Klens[b];

    // fully masked q-tile -> uniform attention -> mean(V)
    if (qt * 16 >= Qlen) {
        const float4* mv = (const float4*)(g_meanV + b * ND);
        #pragma unroll
        for (int i = 0; i < 16; ++i) {
            const int id = tid + i * 256;
            const int row = id >> 8, c4 = id & 255;
            ((float4*)(Out + ((size_t)(b * NQT + qt * 16 + row)) * ND))[c4] = mv[c4];
        }
        return;
    }

    const float* Vb = V + (size_t)b * NKT * ND;
    const unsigned int sb = (unsigned int)__cvta_generic_to_shared(smf);
    const int nT = (Klen + 31) >> 5;

    if (tid < 16) smf[OFF_MRUN + tid] = NEG_INF;

    // prologue: V half0 of tile0 into buffer A
    fill_vhalf(sb, OFF_VA, Vb, 0, 0, tid);
    cp_commit();

    // PV state: 2 groups x 8 rows; thread owns float4 {gt2, gt2+128} of d
    const int g2 = tid >> 7, gt2 = tid & 127;
    unsigned long long o2[32];     // [row r][4]: hh*2 + {0,1}
    #pragma unroll
    for (int i = 0; i < 32; ++i) o2[i] = 0ull;
    float m[8], l[8];
    #pragma unroll
    for (int r = 0; r < 8; ++r) { m[r] = NEG_INF; l[r] = 0.f; }

    const uint4* Abase = g_QA + (size_t)(b * 128 + qt) * 4096 + (size_t)(h * 32) * 64 + lane;

    for (int t = 0; t < nT; ++t) {
        const int tn1 = (t + 1 < nT) ? t + 1 : t;

        // V half1 of this tile into buffer B
        fill_vhalf(sb, OFF_VB, Vb, t, 1, tid);
        cp_commit();

        // ---- QK: bf16 3-pass MMA over this warp's 32 d-chunks ----
        {
            const uint4* Ap = Abase;
            const uint2* Bp = g_KB + (size_t)(b * 256 + t * 4 + wn) * 4096
                              + (size_t)(h * 32) * 64 + lane;
            float c0 = 0.f, c1 = 0.f, c2 = 0.f, c3 = 0.f;
            #pragma unroll 8
            for (int cc = 0; cc < 32; ++cc) {
                const uint4 Ah = Ap[0];
                const uint4 Al = Ap[32];
                const uint2 Bh = Bp[0];
                const uint2 Bl = Bp[32];
                Ap += 64; Bp += 64;
                mma_bf16(c0, c1, c2, c3, Ah, Bh.x, Bh.y);
                mma_bf16(c0, c1, c2, c3, Ah, Bl.x, Bl.y);
                mma_bf16(c0, c1, c2, c3, Al, Bh.x, Bh.y);
            }
            float* S = smf + (h ? OFF_S1 : OFF_S0);
            const int r0 = lane >> 2, cA = wn * 8 + (lane & 3) * 2;
            S[r0 * 36 + cA] = c0;       S[r0 * 36 + cA + 1] = c1;
            S[(r0 + 8) * 36 + cA] = c2; S[(r0 + 8) * 36 + cA + 1] = c3;
        }
        __syncthreads();   // s1: scores visible

        // ---- softmax bookkeeping (threads 0..127) ----
        if (tid < 128) {
            const int row = tid >> 3, tc = tid & 7, cb = tc * 4;
            const float4 sa = *(const float4*)(smf + OFF_S0 + row * 36 + cb);
            const float4 sbv = *(const float4*)(smf + OFF_S1 + row * 36 + cb);
            float sv[4] = {sa.x + sbv.x, sa.y + sbv.y, sa.z + sbv.z, sa.w + sbv.w};
            const int colg = t * 32 + cb;
            #pragma unroll
            for (int i = 0; i < 4; ++i) if (colg + i >= Klen) sv[i] = NEG_INF;
            float mx = fmaxf(fmaxf(sv[0], sv[1]), fmaxf(sv[2], sv[3]));
            mx = fmaxf(mx, __shfl_xor_sync(0xffffffffu, mx, 1));
            mx = fmaxf(mx, __shfl_xor_sync(0xffffffffu, mx, 2));
            mx = fmaxf(mx, __shfl_xor_sync(0xffffffffu, mx, 4));
            const float mN = fmaxf(smf[OFF_MRUN + row], mx);
            float ps = 0.f;
            #pragma unroll
            for (int i = 0; i < 4; ++i) {
                const float p = __expf(sv[i] - mN);   // -inf -> 0
                smf[OFF_PT + (cb + i) * 20 + row] = p;
                ps += p;
            }
            ps += __shfl_xor_sync(0xffffffffu, ps, 1);
            ps += __shfl_xor_sync(0xffffffffu, ps, 2);
            ps += __shfl_xor_sync(0xffffffffu, ps, 4);
            if (tc == 0) {
                smf[OFF_MNEW + row] = mN;
                smf[OFF_LT + row]   = ps;
                smf[OFF_MRUN + row] = mN;
            }
        }
        cp_wait1();        // buffer A (V half0 of tile t) done
        __syncthreads();   // s2: softmax results + V half0 visible

        // ---- rescale accumulators to the new max ----
        #pragma unroll
        for (int r = 0; r < 8; ++r) {
            const float mN = smf[OFF_MNEW + 8 * g2 + r];
            const float sc = __expf(m[r] - mN);
            l[r] = l[r] * sc + smf[OFF_LT + 8 * g2 + r];
            m[r] = mN;
            F2U s2v; s2v.f.x = sc; s2v.f.y = sc;
            #pragma unroll
            for (int u = 0; u < 4; ++u) o2[r * 4 + u] = fmul2(o2[r * 4 + u], s2v.u);
        }

        // ---- PV d-half 0 (buffer A) ----
        {
            const ulonglong2* vb = (const ulonglong2*)(smf + OFF_VA);
            #pragma unroll 4
            for (int j = 0; j < 32; ++j) {
                const ulonglong2 vv = vb[j * 128 + gt2];
                const float4 pA = *(const float4*)(smf + OFF_PT + j * 20 + 8 * g2);
                const float4 pB = *(const float4*)(smf + OFF_PT + j * 20 + 8 * g2 + 4);
                const float pr[8] = {pA.x, pA.y, pA.z, pA.w, pB.x, pB.y, pB.z, pB.w};
                #pragma unroll
                for (int r = 0; r < 8; ++r) {
                    F2U pp; pp.f.x = pr[r]; pp.f.y = pr[r];
                    ffma2(o2[r * 4 + 0], pp.u, vv.x);
                    ffma2(o2[r * 4 + 1], pp.u, vv.y);
                }
            }
        }
        __syncthreads();   // s3: buffer A free

        fill_vhalf(sb, OFF_VA, Vb, tn1, 0, tid);   // prefetch next tile's half0
        cp_commit();
        cp_wait1();        // buffer B (V half1 of tile t) done
        __syncthreads();   // s4: V half1 visible

        // ---- PV d-half 1 (buffer B) ----
        {
            const ulonglong2* vb = (const ulonglong2*)(smf + OFF_VB);
            #pragma unroll 4
            for (int j = 0; j < 32; ++j) {
                const ulonglong2 vv = vb[j * 128 + gt2];
                const float4 pA = *(const float4*)(smf + OFF_PT + j * 20 + 8 * g2);
                const float4 pB = *(const float4*)(smf + OFF_PT + j * 20 + 8 * g2 + 4);
                const float pr[8] = {pA.x, pA.y, pA.z, pA.w, pB.x, pB.y, pB.z, pB.w};
                #pragma unroll
                for (int r = 0; r < 8; ++r) {
                    F2U pp; pp.f.x = pr[r]; pp.f.y = pr[r];
                    ffma2(o2[r * 4 + 2], pp.u, vv.x);
                    ffma2(o2[r * 4 + 3], pp.u, vv.y);
                }
            }
        }
        __syncthreads();   // s5: buffer B + P free for next tile
    }

    // ---- epilogue ----
    const float4* mv = (const float4*)(g_meanV + b * ND);
    #pragma unroll
    for (int r = 0; r < 8; ++r) {
        const int qrow = qt * 16 + 8 * g2 + r;
        float4* op = (float4*)(Out + ((size_t)(b * NQT + qrow)) * ND);
        if (qrow < Qlen) {
            const float inv = 1.0f / l[r];
            F2U iv; iv.f.x = inv; iv.f.y = inv;
            ulonglong2 w0, w1;
            w0.x = fmul2(o2[r * 4 + 0], iv.u); w0.y = fmul2(o2[r * 4 + 1], iv.u);
            w1.x = fmul2(o2[r * 4 + 2], iv.u); w1.y = fmul2(o2[r * 4 + 3], iv.u);
            ((ulonglong2*)op)[gt2]       = w0;
            ((ulonglong2*)op)[gt2 + 128] = w1;
        } else {
            op[gt2]       = mv[gt2];
            op[gt2 + 128] = mv[gt2 + 128];
        }
    }
}

extern "C" void kernel_launch(void* const* d_in, const int* in_sizes, int n_in,
                              void* d_out, int out_size) {
    (void)in_sizes; (void)n_in; (void)out_size;
    const float* Q  = (const float*)d_in[0];
    const float* K  = (const float*)d_in[1];
    const float* V  = (const float*)d_in[2];
    const int*   Ql = (const int*)d_in[3];
    const int*   Kl = (const int*)d_in[4];
    float* Out = (float*)d_out;

    meanv_kernel<<<dim3(ND / 64, NB), 256>>>(V);

    cudaFuncSetAttribute((const void*)qpack_kernel,
                         cudaFuncAttributeMaxDynamicSharedMemorySize, 16 * ND * 4);
    qpack_kernel<<<dim3(128, NB), 256, 16 * ND * 4>>>(Q);
    kpack_kernel<<<dim3(256, NB), 256>>>(K);

    const int smem_bytes = SMEM_FLOATS * 4;   // 138,432 B
    cudaFuncSetAttribute((const void*)attn_kernel,
                         cudaFuncAttributeMaxDynamicSharedMemorySize, smem_bytes);
    attn_kernel<<<dim3(128, NB), NTHREADS, smem_bytes>>>(V, Ql, Kl, Out);
}

// round 7
// speedup vs baseline: 3.4748x; 1.2848x over previous
#include <cuda_runtime.h>
#include <cuda_bf16.h>
#include <cuda_fp16.h>
#include <cstdint>

#define NB 16
#define NQT 2048
#define NKT 2048
#define ND 1024
#define NTHREADS 256

#define NEG_INF __int_as_float(0xff800000)

// ---- device-global scratch (no cudaMalloc allowed) ----
// Q A-fragments (bf16 hi/lo): [b][qtile16(128)][chunk16(64)][hi/lo(2)][lane(32)] uint4 = 134 MB
__device__ uint4 g_QA[16 * 128 * 64 * 2 * 32];
// K B-fragments (bf16 hi/lo): [b][ntile8(256)][chunk16(64)][hi/lo(2)][lane(32)] uint2 = 67 MB
__device__ uint2 g_KB[16 * 256 * 64 * 2 * 32];
// V B-fragments (fp16): [b][kchunk16(128)][ntile8(128)][lane(32)] uint2 = 64 MB
__device__ uint2 g_VH[16 * 128 * 128 * 32];
__device__ float g_meanV[NB * ND];

__device__ __forceinline__ void mma_bf16(float& c0, float& c1, float& c2, float& c3,
                                         const uint4& a, unsigned b0, unsigned b1) {
    asm volatile("mma.sync.aligned.m16n8k16.row.col.f32.bf16.bf16.f32 "
                 "{%0,%1,%2,%3},{%4,%5,%6,%7},{%8,%9},{%0,%1,%2,%3};"
                 : "+f"(c0), "+f"(c1), "+f"(c2), "+f"(c3)
                 : "r"(a.x), "r"(a.y), "r"(a.z), "r"(a.w), "r"(b0), "r"(b1));
}
__device__ __forceinline__ void mma_f16(float& c0, float& c1, float& c2, float& c3,
                                        const uint4& a, unsigned b0, unsigned b1) {
    asm volatile("mma.sync.aligned.m16n8k16.row.col.f32.f16.f16.f32 "
                 "{%0,%1,%2,%3},{%4,%5,%6,%7},{%8,%9},{%0,%1,%2,%3};"
                 : "+f"(c0), "+f"(c1), "+f"(c2), "+f"(c3)
                 : "r"(a.x), "r"(a.y), "r"(a.z), "r"(a.w), "r"(b0), "r"(b1));
}

__device__ __forceinline__ unsigned pack_bf16(float a, float b) {
    __nv_bfloat162 t = __floats2bfloat162_rn(a, b);
    unsigned r; memcpy(&r, &t, 4); return r;
}
__device__ __forceinline__ unsigned pack_f16(float a, float b) {
    __half2 t = __floats2half2_rn(a, b);
    unsigned r; memcpy(&r, &t, 4); return r;
}
__device__ __forceinline__ float bf16_res(float x) {
    return x - __bfloat162float(__float2bfloat16_rn(x));
}

// ---------------- precompute kernels ----------------

__global__ void meanv_kernel(const float* __restrict__ V) {
    __shared__ float red[256];
    const int b = blockIdx.y;
    const int d = blockIdx.x * 64 + (threadIdx.x & 63);
    const int kc = threadIdx.x >> 6;
    const float* vp = V + ((size_t)b * NKT + (size_t)kc * 512) * ND + d;
    float s = 0.f;
    #pragma unroll 8
    for (int k = 0; k < 512; ++k) s += vp[(size_t)k * ND];
    red[threadIdx.x] = s;
    __syncthreads();
    if (threadIdx.x < 64) {
        float tot = red[threadIdx.x] + red[threadIdx.x + 64]
                  + red[threadIdx.x + 128] + red[threadIdx.x + 192];
        g_meanV[b * ND + blockIdx.x * 64 + threadIdx.x] = tot * (1.0f / (float)NKT);
    }
}

__global__ void qpack_kernel(const float* __restrict__ Q) {
    extern __shared__ float sq[];   // [16][1024]
    const int qt = blockIdx.x, b = blockIdx.y, tid = threadIdx.x;
    const float4* src = (const float4*)(Q + ((size_t)(b * NQT + qt * 16)) * ND);
    #pragma unroll
    for (int i = 0; i < 16; ++i) ((float4*)sq)[tid + i * 256] = src[tid + i * 256];
    __syncthreads();
    const size_t base = (size_t)(b * 128 + qt) * 4096;
    #pragma unroll
    for (int it = 0; it < 16; ++it) {
        const int id = tid + it * 256;
        const int rec = id >> 5, lane = id & 31;
        const int ch = rec >> 1, hl = rec & 1;
        const int r0 = lane >> 2, c = ch * 16 + (lane & 3) * 2;
        float v0 = sq[r0 * ND + c],           v1 = sq[r0 * ND + c + 1];
        float v2 = sq[(r0 + 8) * ND + c],     v3 = sq[(r0 + 8) * ND + c + 1];
        float v4 = sq[r0 * ND + c + 8],       v5 = sq[r0 * ND + c + 9];
        float v6 = sq[(r0 + 8) * ND + c + 8], v7 = sq[(r0 + 8) * ND + c + 9];
        if (hl) {
            v0 = bf16_res(v0); v1 = bf16_res(v1); v2 = bf16_res(v2); v3 = bf16_res(v3);
            v4 = bf16_res(v4); v5 = bf16_res(v5); v6 = bf16_res(v6); v7 = bf16_res(v7);
        }
        uint4 o;
        o.x = pack_bf16(v0, v1); o.y = pack_bf16(v2, v3);
        o.z = pack_bf16(v4, v5); o.w = pack_bf16(v6, v7);
        g_QA[base + (size_t)rec * 32 + lane] = o;
    }
}

__global__ void kpack_kernel(const float* __restrict__ K) {
    __shared__ float sk[8 * ND];
    const int nt = blockIdx.x, b = blockIdx.y, tid = threadIdx.x;
    const float4* src = (const float4*)(K + ((size_t)(b * NKT + nt * 8)) * ND);
    #pragma unroll
    for (int i = 0; i < 8; ++i) ((float4*)sk)[tid + i * 256] = src[tid + i * 256];
    __syncthreads();
    const size_t base = (size_t)(b * 256 + nt) * 4096;
    #pragma unroll
    for (int it = 0; it < 16; ++it) {
        const int id = tid + it * 256;
        const int rec = id >> 5, lane = id & 31;
        const int ch = rec >> 1, hl = rec & 1;
        const int n = lane >> 2, c = ch * 16 + (lane & 3) * 2;
        float v0 = sk[n * ND + c],     v1 = sk[n * ND + c + 1];
        float v2 = sk[n * ND + c + 8], v3 = sk[n * ND + c + 9];
        if (hl) { v0 = bf16_res(v0); v1 = bf16_res(v1); v2 = bf16_res(v2); v3 = bf16_res(v3); }
        uint2 o;
        o.x = pack_bf16(v0, v1); o.y = pack_bf16(v2, v3);
        g_KB[base + (size_t)rec * 32 + lane] = o;
    }
}

// V -> fp16 B-fragments for PV (m16n8k16: B[k][n] with k=V row, n=d col)
__global__ void vpack_kernel(const float* __restrict__ V) {
    extern __shared__ float sv[];   // [16][1024]
    const int kc = blockIdx.x, b = blockIdx.y, tid = threadIdx.x;
    const float4* src = (const float4*)(V + ((size_t)(b * NKT + kc * 16)) * ND);
    #pragma unroll
    for (int i = 0; i < 16; ++i) ((float4*)sv)[tid + i * 256] = src[tid + i * 256];
    __syncthreads();
    const size_t base = (size_t)(b * 128 + kc) * 4096;   // 128 ntiles * 32 lanes
    #pragma unroll
    for (int it = 0; it < 16; ++it) {
        const int id = tid + it * 256;
        const int nt = id >> 5, lane = id & 31;
        const int g = lane >> 2, k0 = (lane & 3) * 2;
        const int col = nt * 8 + g;
        float v0 = sv[k0 * ND + col],       v1 = sv[(k0 + 1) * ND + col];
        float v2 = sv[(k0 + 8) * ND + col], v3 = sv[(k0 + 9) * ND + col];
        uint2 o;
        o.x = pack_f16(v0, v1); o.y = pack_f16(v2, v3);
        g_VH[base + id] = o;
    }
}

// ---------------- attention kernel ----------------

__global__ void __launch_bounds__(NTHREADS, 2)
attn_kernel(const int* __restrict__ Qlens, const int* __restrict__ Klens,
            float* __restrict__ Out)
{
    __shared__ float sS[2][2][16 * 36];   // [buf][d-half][row][col(+pad)]
    __shared__ uint4 sP[2][2][32];        // [buf][chunk][lane] P A-fragments (fp16)
    __shared__ float sM[16];              // running max
    __shared__ float sL[16];              // running denom
    __shared__ float sSC[2][16];          // per-tile rescale factor

    const int tid  = threadIdx.x;
    const int qt   = blockIdx.x;
    const int b    = blockIdx.y;
    const int lane = tid & 31;
    const int w    = tid >> 5;
    const int h    = w >> 2;       // d-half for QK
    const int wn   = w & 3;        // n-tile (8 cols) for QK
    const int g    = lane >> 2;    // MMA groupID
    const int tig  = lane & 3;

    const int Qlen = Qlens[b];
    const int Klen = Klens[b];

    // fully masked q-tile -> uniform attention -> mean(V)
    if (qt * 16 >= Qlen) {
        const float4* mv = (const float4*)(g_meanV + b * ND);
        #pragma unroll
        for (int i = 0; i < 16; ++i) {
            const int id = tid + i * 256;
            const int row = id >> 8, c4 = id & 255;
            ((float4*)(Out + ((size_t)(b * NQT + qt * 16 + row)) * ND))[c4] = mv[c4];
        }
        return;
    }

    if (tid < 16) { sM[tid] = NEG_INF; sL[tid] = 0.f; }
    __syncthreads();

    const int nT = (Klen + 31) >> 5;

    // PV accumulators: warp owns d-cols [w*128, w*128+128) = 16 n8-tiles
    float acc[16][4];
    #pragma unroll
    for (int i = 0; i < 16; ++i)
        #pragma unroll
        for (int u = 0; u < 4; ++u) acc[i][u] = 0.f;

    const uint4* Abase = g_QA + (size_t)(b * 128 + qt) * 4096 + (size_t)(h * 32) * 64 + lane;

    for (int t = 0; t < nT; ++t) {
        const int buf = t & 1;

        // ---- QK: bf16 3-pass MMA over this warp's 32 d-chunks ----
        {
            const uint4* Ap = Abase;
            const uint2* Bp = g_KB + (size_t)(b * 256 + t * 4 + wn) * 4096
                              + (size_t)(h * 32) * 64 + lane;
            float c0 = 0.f, c1 = 0.f, c2 = 0.f, c3 = 0.f;
            #pragma unroll 8
            for (int cc = 0; cc < 32; ++cc) {
                const uint4 Ah = Ap[0];
                const uint4 Al = Ap[32];
                const uint2 Bh = Bp[0];
                const uint2 Bl = Bp[32];
                Ap += 64; Bp += 64;
                mma_bf16(c0, c1, c2, c3, Ah, Bh.x, Bh.y);
                mma_bf16(c0, c1, c2, c3, Ah, Bl.x, Bl.y);
                mma_bf16(c0, c1, c2, c3, Al, Bh.x, Bh.y);
            }
            float* S = sS[buf][h];
            const int cA = wn * 8 + tig * 2;
            *(float2*)(S + g * 36 + cA)       = make_float2(c0, c1);
            *(float2*)(S + (g + 8) * 36 + cA) = make_float2(c2, c3);
        }
        __syncthreads();   // s1: scores visible; prev tile's PV done everywhere

        // ---- softmax (threads 0..127): P fragments (fp16), sc, m, l ----
        if (tid < 128) {
            const int row = tid >> 3, tc = tid & 7, cb = tc * 4;
            const float4 sa  = *(const float4*)(sS[buf][0] + row * 36 + cb);
            const float4 sbv = *(const float4*)(sS[buf][1] + row * 36 + cb);
            float sv[4] = {sa.x + sbv.x, sa.y + sbv.y, sa.z + sbv.z, sa.w + sbv.w};
            const int colg = t * 32 + cb;
            #pragma unroll
            for (int i = 0; i < 4; ++i) if (colg + i >= Klen) sv[i] = NEG_INF;
            const float mOld = sM[row];
            float mx = fmaxf(fmaxf(sv[0], sv[1]), fmaxf(sv[2], sv[3]));
            mx = fmaxf(mx, __shfl_xor_sync(0xffffffffu, mx, 1));
            mx = fmaxf(mx, __shfl_xor_sync(0xffffffffu, mx, 2));
            mx = fmaxf(mx, __shfl_xor_sync(0xffffffffu, mx, 4));
            const float mN = fmaxf(mOld, mx);
            // probabilities, rounded to fp16 (l accumulates the rounded values)
            float p[4];
            #pragma unroll
            for (int i = 0; i < 4; ++i)
                p[i] = __half2float(__float2half_rn(__expf(sv[i] - mN)));
            float ps = (p[0] + p[1]) + (p[2] + p[3]);
            ps += __shfl_xor_sync(0xffffffffu, ps, 1);
            ps += __shfl_xor_sync(0xffffffffu, ps, 2);
            ps += __shfl_xor_sync(0xffffffffu, ps, 4);
            // write P into A-fragment slots
            const int chunk = cb >> 4;
            const int cw = cb & 15;
            const int reg = ((cw >= 8) ? 2 : 0) + ((row >= 8) ? 1 : 0);
            const int lane0 = (row & 7) * 4 + ((cw & 7) >> 1);
            unsigned* pu = (unsigned*)sP[buf][chunk];
            pu[lane0 * 4 + reg]       = pack_f16(p[0], p[1]);
            pu[(lane0 + 1) * 4 + reg] = pack_f16(p[2], p[3]);
            if (tc == 0) {
                const float sc = __expf(mOld - mN);   // -inf -> 0 on first tile
                sSC[buf][row] = sc;
                sM[row] = mN;
                sL[row] = sL[row] * sc + ps;
            }
        }
        __syncthreads();   // s2: P, sc visible

        // ---- PV: rescale acc, then fp16 MMA over 2 k-chunks x 16 n-tiles ----
        {
            const float sc0 = sSC[buf][g];
            const float sc1 = sSC[buf][g + 8];
            #pragma unroll
            for (int i = 0; i < 16; ++i) {
                acc[i][0] *= sc0; acc[i][1] *= sc0;
                acc[i][2] *= sc1; acc[i][3] *= sc1;
            }
            #pragma unroll
            for (int cc = 0; cc < 2; ++cc) {
                const uint4 A = sP[buf][cc][lane];
                const uint2* vb = g_VH + ((size_t)(b * 128 + t * 2 + cc) * 128 + w * 16) * 32 + lane;
                #pragma unroll
                for (int i = 0; i < 16; ++i) {
                    const uint2 B = vb[i * 32];
                    mma_f16(acc[i][0], acc[i][1], acc[i][2], acc[i][3], A, B.x, B.y);
                }
            }
        }
        // no sync: next iteration's s1 protects buffers (double-buffered S/P/sc)
    }

    // ---- epilogue ----
    const float invA = 1.0f / sL[g];
    const float invB = 1.0f / sL[g + 8];
    const bool vA = (qt * 16 + g) < Qlen;
    const bool vB = (qt * 16 + g + 8) < Qlen;
    float* outA = Out + ((size_t)(b * NQT + qt * 16 + g)) * ND;
    float* outB = Out + ((size_t)(b * NQT + qt * 16 + g + 8)) * ND;
    const float* mv = g_meanV + b * ND;
    #pragma unroll
    for (int i = 0; i < 16; ++i) {
        const int col = w * 128 + i * 8 + tig * 2;
        float2 w0, w1;
        if (vA) { w0.x = acc[i][0] * invA; w0.y = acc[i][1] * invA; }
        else    { w0 = *(const float2*)(mv + col); }
        if (vB) { w1.x = acc[i][2] * invB; w1.y = acc[i][3] * invB; }
        else    { w1 = *(const float2*)(mv + col); }
        *(float2*)(outA + col) = w0;
        *(float2*)(outB + col) = w1;
    }
}

extern "C" void kernel_launch(void* const* d_in, const int* in_sizes, int n_in,
                              void* d_out, int out_size) {
    (void)in_sizes; (void)n_in; (void)out_size;
    const float* Q  = (const float*)d_in[0];
    const float* K  = (const float*)d_in[1];
    const float* V  = (const float*)d_in[2];
    const int*   Ql = (const int*)d_in[3];
    const int*   Kl = (const int*)d_in[4];
    float* Out = (float*)d_out;

    meanv_kernel<<<dim3(ND / 64, NB), 256>>>(V);

    cudaFuncSetAttribute((const void*)qpack_kernel,
                         cudaFuncAttributeMaxDynamicSharedMemorySize, 16 * ND * 4);
    qpack_kernel<<<dim3(128, NB), 256, 16 * ND * 4>>>(Q);
    kpack_kernel<<<dim3(256, NB), 256>>>(K);
    cudaFuncSetAttribute((const void*)vpack_kernel,
                         cudaFuncAttributeMaxDynamicSharedMemorySize, 16 * ND * 4);
    vpack_kernel<<<dim3(128, NB), 256, 16 * ND * 4>>>(V);

    attn_kernel<<<dim3(128, NB), NTHREADS>>>(Ql, Kl, Out);
}